// round 2
// baseline (speedup 1.0000x reference)
#include <cuda_runtime.h>
#include <cuda_bf16.h>

// time_embeddings: out[b, i] = sin/cos(time[b] * 10000^(-(i//2)/640))
// B = 65536, DIM = 1280, fp32 out. Pure HBM-store-bound (~335.5 MB out).
//
// Round-2 changes vs round-1 (55.4us):
//  - BLOCK=320: thread <-> chunk is 1:1, each block writes one FULL row
//    (5120 B contiguous) per iteration. Perfect coalescing, zero modulo math.
//  - grid = 148 SMs * 6 blocks = 888 = exactly ONE wave (60 warps/SM),
//    grid-stride over rows -> no wave-quantization tail.
//  - row unroll x2: two independent time loads + two stores per iteration
//    for store MLP and L2-load latency hiding.

#define DIM      1280
#define CHUNKS   (DIM / 4)     // 320 float4 per row
#define BLOCK    CHUNKS        // 320 threads, one chunk per thread
#define GRID     888           // 148 SMs * 6 blocks  == one full wave

__global__ __launch_bounds__(BLOCK, 6)
void time_emb_kernel(const float* __restrict__ time, float4* __restrict__ out, int B)
{
    const int chunk = threadIdx.x;          // 0..319

    // rate(p) = 10000^(-p/640) = exp2(-log2(10000)/640 * p), p = i//2
    const float C = -13.287712379549449f / 640.0f;
    const int p0 = 2 * chunk;
    const float rate0 = exp2f(C * (float)(p0));
    const float rate1 = exp2f(C * (float)(p0 + 1));

    // Cody-Waite: 2*pi = HI + LO, HI=6.28125 exact for k<=160 (angle<=1000)
    const float INV2PI = 0.15915494309189535f;
    const float HI     = 6.28125f;
    const float LO     = 1.9353071795864769e-3f;

    const int G = gridDim.x;
    int row = blockIdx.x;

    // main loop: two rows per iteration
    for (; row + G < B; row += 2 * G) {
        const float t0 = __ldg(&time[row]);
        const float t1 = __ldg(&time[row + G]);

        float a00 = t0 * rate0, a01 = t0 * rate1;
        float a10 = t1 * rate0, a11 = t1 * rate1;

        float k00 = rintf(a00 * INV2PI), k01 = rintf(a01 * INV2PI);
        float k10 = rintf(a10 * INV2PI), k11 = rintf(a11 * INV2PI);

        float x00 = fmaf(k00, -LO, fmaf(k00, -HI, a00));
        float x01 = fmaf(k01, -LO, fmaf(k01, -HI, a01));
        float x10 = fmaf(k10, -LO, fmaf(k10, -HI, a10));
        float x11 = fmaf(k11, -LO, fmaf(k11, -HI, a11));

        float4 v0, v1;
        __sincosf(x00, &v0.x, &v0.y);
        __sincosf(x01, &v0.z, &v0.w);
        __sincosf(x10, &v1.x, &v1.y);
        __sincosf(x11, &v1.z, &v1.w);

        __stcs(&out[(size_t)row * CHUNKS + chunk], v0);
        __stcs(&out[(size_t)(row + G) * CHUNKS + chunk], v1);
    }

    // tail: at most one row remaining for this block
    if (row < B) {
        const float t = __ldg(&time[row]);
        float a0 = t * rate0, a1 = t * rate1;
        float k0 = rintf(a0 * INV2PI), k1 = rintf(a1 * INV2PI);
        float x0 = fmaf(k0, -LO, fmaf(k0, -HI, a0));
        float x1 = fmaf(k1, -LO, fmaf(k1, -HI, a1));
        float4 v;
        __sincosf(x0, &v.x, &v.y);
        __sincosf(x1, &v.z, &v.w);
        __stcs(&out[(size_t)row * CHUNKS + chunk], v);
    }
}

extern "C" void kernel_launch(void* const* d_in, const int* in_sizes, int n_in,
                              void* d_out, int out_size)
{
    const float* time = (const float*)d_in[0];
    float4* out = (float4*)d_out;
    const int B = in_sizes[0];

    time_emb_kernel<<<GRID, BLOCK>>>(time, out, B);
}

// round 3
// speedup vs baseline: 1.1160x; 1.1160x over previous
#include <cuda_runtime.h>
#include <cuda_bf16.h>

// time_embeddings: out[b, i] = sin/cos(time[b] * 10000^(-(i//2)/640))
// B = 65536, DIM = 1280, fp32 out. Pure HBM-store-bound (~335.5 MB out).
//
// Round-3: keep round-2's full-row blocks (BLOCK=320, one float4 chunk per
// thread, 5120B contiguous per block-iteration) + x2 row unroll, but use
// grid = 3552 (4 scheduling waves of 6-blocks/SM residency) instead of a
// single exact wave. Medium-grain blocks (~18 rows each) let the work
// distributor absorb per-SM skew that serialized the one-wave version in
// the timed (back-to-back graph replay) regime.

#define DIM      1280
#define CHUNKS   (DIM / 4)     // 320 float4 per row
#define BLOCK    CHUNKS        // 320 threads, one chunk per thread
#define GRID     3552          // 148 SMs * 6 resident * 4 waves

__global__ __launch_bounds__(BLOCK, 6)
void time_emb_kernel(const float* __restrict__ time, float4* __restrict__ out, int B)
{
    const int chunk = threadIdx.x;          // 0..319

    // rate(p) = 10000^(-p/640) = exp2(-log2(10000)/640 * p), p = i//2
    const float C = -13.287712379549449f / 640.0f;
    const int p0 = 2 * chunk;
    const float rate0 = exp2f(C * (float)(p0));
    const float rate1 = exp2f(C * (float)(p0 + 1));

    // Cody-Waite: 2*pi = HI + LO, HI=6.28125 exact for k<=160 (angle<=1000)
    const float INV2PI = 0.15915494309189535f;
    const float HI     = 6.28125f;
    const float LO     = 1.9353071795864769e-3f;

    const int G = GRID;
    int row = blockIdx.x;

    // main loop: two rows per iteration (independent chains, 2 stores in flight)
    for (; row + G < B; row += 2 * G) {
        const float t0 = __ldg(&time[row]);
        const float t1 = __ldg(&time[row + G]);

        float a00 = t0 * rate0, a01 = t0 * rate1;
        float a10 = t1 * rate0, a11 = t1 * rate1;

        float k00 = rintf(a00 * INV2PI), k01 = rintf(a01 * INV2PI);
        float k10 = rintf(a10 * INV2PI), k11 = rintf(a11 * INV2PI);

        float x00 = fmaf(k00, -LO, fmaf(k00, -HI, a00));
        float x01 = fmaf(k01, -LO, fmaf(k01, -HI, a01));
        float x10 = fmaf(k10, -LO, fmaf(k10, -HI, a10));
        float x11 = fmaf(k11, -LO, fmaf(k11, -HI, a11));

        float4 v0, v1;
        __sincosf(x00, &v0.x, &v0.y);
        __sincosf(x01, &v0.z, &v0.w);
        __sincosf(x10, &v1.x, &v1.y);
        __sincosf(x11, &v1.z, &v1.w);

        __stcs(&out[(size_t)row * CHUNKS + chunk], v0);
        __stcs(&out[(size_t)(row + G) * CHUNKS + chunk], v1);
    }

    // tail: at most one row remaining for this block
    if (row < B) {
        const float t = __ldg(&time[row]);
        float a0 = t * rate0, a1 = t * rate1;
        float k0 = rintf(a0 * INV2PI), k1 = rintf(a1 * INV2PI);
        float x0 = fmaf(k0, -LO, fmaf(k0, -HI, a0));
        float x1 = fmaf(k1, -LO, fmaf(k1, -HI, a1));
        float4 v;
        __sincosf(x0, &v.x, &v.y);
        __sincosf(x1, &v.z, &v.w);
        __stcs(&out[(size_t)row * CHUNKS + chunk], v);
    }
}

extern "C" void kernel_launch(void* const* d_in, const int* in_sizes, int n_in,
                              void* d_out, int out_size)
{
    const float* time = (const float*)d_in[0];
    float4* out = (float4*)d_out;
    const int B = in_sizes[0];

    time_emb_kernel<<<GRID, BLOCK>>>(time, out, B);
}